// round 14
// baseline (speedup 1.0000x reference)
#include <cuda_runtime.h>
#include <cuda_fp16.h>
#include <cstdint>

// ---------------- problem constants -----------------------------------------
#define DD    256
#define NNODE 20000
#define RRR   12
#define EE    200000
#define NB    (2*RRR)
#define TM    128
#define MAX_TILES (2*EE/TM + NB + 8)   // scratch sizing (quad table is smaller)
#define NCHUNK 4             // K=256 as 4 k64 chunks, single fp16 pass
#define QUAD  4              // M-tiles per CTA (B loaded once per CTA)

// ---------------- smem layout -------------------------------------------------
#define SM_ROWSRC 0          // 128 int
#define SM_ROWDST 512        // 128 int
#define SM_BIAS   1024       // 128 float
#define SM_BUF    2048       // A stages: 2 x 16KB
#define A_STRIDE  16384
#define OFF_BRES  (SM_BUF + 2*A_STRIDE)     // resident B: 4 chunks x 16KB = 64KB
#define SMEM_TOTAL (OFF_BRES + 4*16384)     // 100352 B -> occ 2 (empirically confirmed)

// ---------------- device scratch ---------------------------------------------
__device__ int g_count[RRR];
__device__ int g_start[NB + 1];
__device__ int g_cursor[NB];
__device__ int g_src[2 * EE];
__device__ int g_dst[2 * EE];
__device__ int g_tile_info[MAX_TILES];
__device__ int g_total_tiles;

__device__ __half g_xh[NNODE * DD];
__device__ __half g_wh[(NB + 1) * DD * DD];   // [bucket][out=n][in=k]; index NB = W_self

// ---------------- PTX helpers ------------------------------------------------
__device__ __forceinline__ uint32_t smem_u32(const void* p) {
    uint32_t a;
    asm("{ .reg .u64 t; cvta.to.shared.u64 t, %1; cvt.u32.u64 %0, t; }" : "=r"(a) : "l"(p));
    return a;
}
__device__ __forceinline__ void cp16(uint32_t d, const void* s) {
    asm volatile("cp.async.cg.shared.global [%0], [%1], 16;" :: "r"(d), "l"(s) : "memory");
}
__device__ __forceinline__ void cp_commit() {
    asm volatile("cp.async.commit_group;" ::: "memory");
}
template<int N> __device__ __forceinline__ void cp_wait() {
    asm volatile("cp.async.wait_group %0;" :: "n"(N) : "memory");
}
__device__ __forceinline__ void ldsm4(uint32_t* r, uint32_t addr) {
    asm volatile("ldmatrix.sync.aligned.m8n8.x4.shared.b16 {%0,%1,%2,%3}, [%4];"
                 : "=r"(r[0]), "=r"(r[1]), "=r"(r[2]), "=r"(r[3]) : "r"(addr));
}
__device__ __forceinline__ void mma16816(float* c, const uint32_t* a, uint32_t b0, uint32_t b1) {
    asm volatile("mma.sync.aligned.m16n8k16.row.col.f32.f16.f16.f32 "
                 "{%0,%1,%2,%3}, {%4,%5,%6,%7}, {%8,%9}, {%0,%1,%2,%3};"
                 : "+f"(c[0]), "+f"(c[1]), "+f"(c[2]), "+f"(c[3])
                 : "r"(a[0]), "r"(a[1]), "r"(a[2]), "r"(a[3]), "r"(b0), "r"(b1));
}
__device__ __forceinline__ void red4(float* p, float a, float b, float c, float d) {
    asm volatile("red.global.add.v4.f32 [%0], {%1,%2,%3,%4};"
                 :: "l"(p), "f"(a), "f"(b), "f"(c), "f"(d) : "memory");
}

// ---------------- setup kernels ----------------------------------------------
__global__ void zero_counts_k() {
    if (threadIdx.x < RRR) g_count[threadIdx.x] = 0;
}

__global__ void hist_k(const int* __restrict__ rel) {
    __shared__ int sc[RRR];
    if (threadIdx.x < RRR) sc[threadIdx.x] = 0;
    __syncthreads();
    int i = blockIdx.x * blockDim.x + threadIdx.x;
    if (i < EE) atomicAdd(&sc[rel[i]], 1);
    __syncthreads();
    if (threadIdx.x < RRR && sc[threadIdx.x])
        atomicAdd(&g_count[threadIdx.x], sc[threadIdx.x]);
}

// scan + QUAD-grouped tile table: one entry = (bucket, first M-tile of quad)
__global__ void scan_k() {
    if (threadIdx.x != 0) return;
    int s = 0, nq = 0;
    for (int b = 0; b < NB; b++) {
        int c = g_count[(b < RRR) ? b : (b - RRR)];
        g_start[b] = s;
        g_cursor[b] = s;
        int ntile = (c + TM - 1) / TM;
        for (int t = 0; t < ntile; t += QUAD) g_tile_info[nq++] = (b << 16) | t;
        s += c;
    }
    g_start[NB] = s;
    g_total_tiles = nq;
}

// block-aggregated scatter: smem local offsets + one global atomic per (block,bucket)
__global__ void scatter2_k(const int* __restrict__ dep,
                           const int* __restrict__ rel,
                           const int* __restrict__ gov) {
    __shared__ int sc[NB];
    __shared__ int base[NB];
    int t = threadIdx.x;
    if (t < NB) sc[t] = 0;
    __syncthreads();
    int i = blockIdx.x * blockDim.x + t;
    int r = 0, d = 0, g = 0, l1 = 0, l2 = 0;
    bool v = (i < EE);
    if (v) {
        r = rel[i]; d = dep[i]; g = gov[i];
        l1 = atomicAdd(&sc[r], 1);
        l2 = atomicAdd(&sc[r + RRR], 1);
    }
    __syncthreads();
    if (t < NB) base[t] = sc[t] ? atomicAdd(&g_cursor[t], sc[t]) : 0;
    __syncthreads();
    if (v) {
        int p = base[r] + l1;         g_src[p] = g; g_dst[p] = d;   // forward
        int q = base[r + RRR] + l2;   g_src[q] = d; g_dst[q] = g;   // reverse
    }
}

// ---------------- fp16 conversions -------------------------------------------
__global__ void convert_x_k(const float* __restrict__ x) {
    int i = blockIdx.x * blockDim.x + threadIdx.x;
    if (i < NNODE * DD) g_xh[i] = __float2half_rn(x[i]);
}

__global__ void convert_w_k(const float* __restrict__ Wr, const float* __restrict__ Ws) {
    int i = blockIdx.x * blockDim.x + threadIdx.x;
    if (i >= (NB + 1) * DD * DD) return;
    int b = i >> 16;
    g_wh[i] = __float2half_rn((b < NB) ? Wr[i] : Ws[i & 65535]);
}

// ---------------- grouped GEMM via mma.sync (HMMA), B-resident quads ----------
// CTA: up to QUAD consecutive 128(M)x128(N) tiles of ONE bucket; grid.y = N half.
// B (full K=256 x 128 N) loaded ONCE into resident smem; A streamed per tile
// through a 2-stage 16KB ring (R8-proven sync pattern). 8 warps, 32x64 tiles.
template<bool SELF>
__global__ __launch_bounds__(256, 2)
void gemm_mma_k(const float* __restrict__ bvec_g, float* __restrict__ out) {
    extern __shared__ char smem[];
    const int tid = threadIdx.x, lid = tid & 31, wid = tid >> 5;
    const int wm = wid >> 1, wn = wid & 1;          // warp grid 4 x 2
    const int n0 = blockIdx.y * 128;

    int b, mt0, start, count;
    if (SELF) {
        b = NB; mt0 = blockIdx.x * QUAD; start = 0; count = NNODE;
    } else {
        if (blockIdx.x >= g_total_tiles) return;
        int info = g_tile_info[blockIdx.x];
        b = info >> 16;
        mt0 = info & 0xFFFF;
        start = g_start[b];
        count = g_start[b + 1] - start;
    }
    const int ntile = (count + TM - 1) / TM;
    const int ng = min(QUAD, ntile - mt0);

    int*   row_src = (int*)smem;
    int*   row_dst = (int*)(smem + SM_ROWDST);
    float* bias    = (float*)(smem + SM_BIAS);
    uint32_t sb = smem_u32(smem);

    if (tid < 128)
        bias[tid] = SELF ? bvec_g[n0 + tid] : bvec_g[b * DD + n0 + tid];

    // resident B fill: 4 chunks x 16KB, one cp.async group (issued up front)
    const __half* Bsrc = g_wh + (size_t)b * DD * DD + (size_t)n0 * DD;
#pragma unroll
    for (int i = 0; i < 16; i++) {
        int u = tid + 256 * i;
        int chunk = u >> 10;
        int v = u & 1023;
        int row = v >> 3, c16 = v & 7;
        uint32_t dsto = (uint32_t)(row * 8 + (c16 ^ (row & 7))) * 16;
        cp16(sb + OFF_BRES + chunk * 16384 + dsto,
             Bsrc + (size_t)row * DD + chunk * 64 + c16 * 8);
    }
    cp_commit();   // group B (retired by the first wait<1> below)

    // A chunk fill into stage s
    auto fillA = [&](int c, int s) {
        int k0 = c * 64;
        uint32_t base = sb + SM_BUF + (uint32_t)s * A_STRIDE;
#pragma unroll
        for (int i = 0; i < 4; i++) {
            int u = tid + 256 * i;
            int row = u >> 3, c16 = u & 7;
            uint32_t dsto = (uint32_t)(row * 8 + (c16 ^ (row & 7))) * 16;
            cp16(base + dsto, g_xh + (size_t)row_src[row] * DD + k0 + c16 * 8);
        }
        cp_commit();
    };

#pragma unroll 1
    for (int g = 0; g < ng; g++) {
        const int m0 = (mt0 + g) * TM;

        __syncthreads();   // prev epilogue reads of row_dst done before regather
        if (tid < 128) {
            int m = m0 + tid; if (m >= count) m = count - 1;
            if (SELF) { row_src[tid] = m;                 row_dst[tid] = m; }
            else      { row_src[tid] = g_src[start + m];  row_dst[tid] = g_dst[start + m]; }
        }
        __syncthreads();

        float acc[2][8][4];
#pragma unroll
        for (int mi = 0; mi < 2; mi++)
#pragma unroll
            for (int j = 0; j < 8; j++)
#pragma unroll
                for (int q = 0; q < 4; q++) acc[mi][j][q] = 0.f;

        fillA(0, 0);
        fillA(1, 1);

#pragma unroll 1
        for (int c = 0; c < NCHUNK; c++) {
            int s = c & 1;
            if (c < NCHUNK - 1) cp_wait<1>(); else cp_wait<0>();
            __syncthreads();

            uint32_t ab = sb + SM_BUF + (uint32_t)s * A_STRIDE;
            uint32_t bb = sb + OFF_BRES + (uint32_t)c * 16384;
#pragma unroll
            for (int ks = 0; ks < 4; ks++) {
                uint32_t a[2][4];
                {
                    int sub = lid >> 3, r8 = lid & 7;
                    int c16 = ks * 2 + (sub >> 1);
#pragma unroll
                    for (int mi = 0; mi < 2; mi++) {
                        int row = wm * 32 + mi * 16 + (sub & 1) * 8 + r8;
                        ldsm4(a[mi], ab + (uint32_t)(row * 8 + (c16 ^ (row & 7))) * 16);
                    }
                }
#pragma unroll
                for (int nj = 0; nj < 4; nj++) {
                    uint32_t bf[4];
                    int grp = lid >> 4, half = (lid >> 3) & 1, r8 = lid & 7;
                    int nrow = wn * 64 + nj * 16 + grp * 8 + r8;
                    int c16 = ks * 2 + half;
                    ldsm4(bf, bb + (uint32_t)(nrow * 8 + (c16 ^ (nrow & 7))) * 16);
#pragma unroll
                    for (int mi = 0; mi < 2; mi++) {
                        mma16816(acc[mi][nj * 2 + 0], a[mi], bf[0], bf[1]);
                        mma16816(acc[mi][nj * 2 + 1], a[mi], bf[2], bf[3]);
                    }
                }
            }
            __syncthreads();                 // all warps done reading A stage s
            if (c + 2 < NCHUNK) fillA(c + 2, s);
        }

        // ---- epilogue: bias + lane-pair merged float4/red4 -------------------
        const int rbase = wm * 32 + (lid >> 2);
        const int cgrp  = lid & 3;
#pragma unroll
        for (int mi = 0; mi < 2; mi++) {
#pragma unroll
            for (int half = 0; half < 2; half++) {
                int rl = rbase + mi * 16 + half * 8;
                bool ok = (m0 + rl) < count;
                int dst = SELF ? (m0 + rl) : row_dst[rl];
                float* orow = out + (size_t)dst * DD + n0;
#pragma unroll
                for (int j = 0; j < 8; j++) {
                    int col = 2 * cgrp + j * 8;
                    float v0 = acc[mi][j][half * 2 + 0] + bias[wn * 64 + col];
                    float v1 = acc[mi][j][half * 2 + 1] + bias[wn * 64 + col + 1];
                    float o0 = __shfl_xor_sync(0xffffffffu, v0, 1);
                    float o1 = __shfl_xor_sync(0xffffffffu, v1, 1);
                    if (ok && !(lid & 1)) {
                        int c4 = wn * 64 + j * 8 + ((cgrp == 0) ? 0 : 4);
                        if (SELF) {
                            float4 v; v.x = v0; v.y = v1; v.z = o0; v.w = o1;
                            *(float4*)(orow + c4) = v;
                        } else {
                            red4(orow + c4, v0, v1, o0, o1);
                        }
                    }
                }
            }
        }
    }
}

// ---------------- final ReLU -------------------------------------------------
__global__ void relu_k(float* __restrict__ out) {
    int i = blockIdx.x * blockDim.x + threadIdx.x;
    if (i < NNODE * DD / 4) {
        float4* p = (float4*)out;
        float4 v = p[i];
        v.x = fmaxf(v.x, 0.f); v.y = fmaxf(v.y, 0.f);
        v.z = fmaxf(v.z, 0.f); v.w = fmaxf(v.w, 0.f);
        p[i] = v;
    }
}

// ---------------- launch -----------------------------------------------------
extern "C" void kernel_launch(void* const* d_in, const int* in_sizes, int n_in,
                              void* d_out, int out_size) {
    (void)in_sizes; (void)n_in; (void)out_size;
    const float* x   = (const float*)d_in[0];
    const int*   dep = (const int*)d_in[1];
    const int*   rel = (const int*)d_in[2];
    const int*   gov = (const int*)d_in[3];
    const float* Ws  = (const float*)d_in[4];
    const float* bs  = (const float*)d_in[5];
    const float* Wr  = (const float*)d_in[6];
    const float* br  = (const float*)d_in[7];
    float* out = (float*)d_out;

    cudaFuncSetAttribute(gemm_mma_k<true>,  cudaFuncAttributeMaxDynamicSharedMemorySize, SMEM_TOTAL);
    cudaFuncSetAttribute(gemm_mma_k<false>, cudaFuncAttributeMaxDynamicSharedMemorySize, SMEM_TOTAL);

    // bucketing (quad-grouped tile table)
    zero_counts_k<<<1, 32>>>();
    hist_k<<<(EE + 255) / 256, 256>>>(rel);
    scan_k<<<1, 32>>>();
    scatter2_k<<<(EE + 255) / 256, 256>>>(dep, rel, gov);

    // fp16 prep
    convert_x_k<<<(NNODE * DD + 255) / 256, 256>>>(x);
    convert_w_k<<<((NB + 1) * DD * DD + 255) / 256, 256>>>(Wr, Ws);

    // self transform (plain stores initialize out): 157 tiles -> 40 quads
    dim3 gself(((NNODE + TM - 1) / TM + QUAD - 1) / QUAD, 2);
    gemm_mma_k<true><<<gself, 256, SMEM_TOTAL>>>(bs, out);

    // grouped message GEMM (+ atomic scatter-add): <=806 quads
    dim3 gmsg((MAX_TILES + QUAD - 1) / QUAD + NB, 2);
    gemm_mma_k<false><<<gmsg, 256, SMEM_TOTAL>>>(br, out);

    relu_k<<<(NNODE * DD / 4 + 255) / 256, 256>>>(out);
}

// round 15
// speedup vs baseline: 1.1513x; 1.1513x over previous
#include <cuda_runtime.h>
#include <cuda_fp16.h>
#include <cstdint>

// ---------------- problem constants -----------------------------------------
#define DD    256
#define NNODE 20000
#define RRR   12
#define EE    200000
#define NB    (2*RRR)
#define TM    128
#define MAX_TILES (2*EE/TM + NB + 8)
#define NCHUNK 4             // single fp16 pass: 4 x k64 chunks (K=256)

// ---------------- smem layout -------------------------------------------------
#define SM_ROWSRC 0          // 128 int
#define SM_ROWDST 512        // 128 int
#define SM_BIAS   1024       // 128 float
#define SM_BUF    2048
#define STAGE_STRIDE 32768   // A 16KB + B 16KB
#define OFF_B     16384
#define NSTAGE    3
#define SMEM_TOTAL (SM_BUF + NSTAGE*STAGE_STRIDE)   // 100352 B -> occ 2, 16 warps/SM

// ---------------- device scratch ---------------------------------------------
__device__ int g_count[RRR];
__device__ int g_start[NB + 1];
__device__ int g_cursor[NB];
__device__ int g_tbase[NB + 1];       // tile-count prefix per bucket
__device__ int g_src[2 * EE];
__device__ int g_dst[2 * EE];
__device__ int g_tile_info[MAX_TILES];
__device__ int g_total_tiles;

__device__ __half g_xh[NNODE * DD];
__device__ __half g_wh[(NB + 1) * DD * DD];   // [bucket][out=n][in=k]; index NB = W_self

// ---------------- PTX helpers ------------------------------------------------
__device__ __forceinline__ uint32_t smem_u32(const void* p) {
    uint32_t a;
    asm("{ .reg .u64 t; cvta.to.shared.u64 t, %1; cvt.u32.u64 %0, t; }" : "=r"(a) : "l"(p));
    return a;
}
__device__ __forceinline__ void cp16(uint32_t d, const void* s) {
    asm volatile("cp.async.cg.shared.global [%0], [%1], 16;" :: "r"(d), "l"(s) : "memory");
}
__device__ __forceinline__ void cp_commit() {
    asm volatile("cp.async.commit_group;" ::: "memory");
}
template<int N> __device__ __forceinline__ void cp_wait() {
    asm volatile("cp.async.wait_group %0;" :: "n"(N) : "memory");
}
__device__ __forceinline__ void ldsm4(uint32_t* r, uint32_t addr) {
    asm volatile("ldmatrix.sync.aligned.m8n8.x4.shared.b16 {%0,%1,%2,%3}, [%4];"
                 : "=r"(r[0]), "=r"(r[1]), "=r"(r[2]), "=r"(r[3]) : "r"(addr));
}
__device__ __forceinline__ void mma16816(float* c, const uint32_t* a, uint32_t b0, uint32_t b1) {
    asm volatile("mma.sync.aligned.m16n8k16.row.col.f32.f16.f16.f32 "
                 "{%0,%1,%2,%3}, {%4,%5,%6,%7}, {%8,%9}, {%0,%1,%2,%3};"
                 : "+f"(c[0]), "+f"(c[1]), "+f"(c[2]), "+f"(c[3])
                 : "r"(a[0]), "r"(a[1]), "r"(a[2]), "r"(a[3]), "r"(b0), "r"(b1));
}
__device__ __forceinline__ void red4(float* p, float a, float b, float c, float d) {
    asm volatile("red.global.add.v4.f32 [%0], {%1,%2,%3,%4};"
                 :: "l"(p), "f"(a), "f"(b), "f"(c), "f"(d) : "memory");
}

// ---------------- fused prep: fp16 converts + count zeroing -------------------
// Runs FIRST (depends on nothing). Block 0 zeroes g_count; all blocks convert.
#define XW_TOTAL (NNODE * DD + (NB + 1) * DD * DD)   // 5.12M + 6.62M
__global__ void convert_all_k(const float* __restrict__ x,
                              const float* __restrict__ Wr,
                              const float* __restrict__ Ws) {
    int i = blockIdx.x * blockDim.x + threadIdx.x;
    if (blockIdx.x == 0 && threadIdx.x < RRR) g_count[threadIdx.x] = 0;
    if (i >= XW_TOTAL) return;
    if (i < NNODE * DD) {
        g_xh[i] = __float2half_rn(x[i]);
    } else {
        int j = i - NNODE * DD;
        int b = j >> 16;
        g_wh[j] = __float2half_rn((b < NB) ? Wr[j] : Ws[j & 65535]);
    }
}

__global__ void hist_k(const int* __restrict__ rel) {
    __shared__ int sc[RRR];
    if (threadIdx.x < RRR) sc[threadIdx.x] = 0;
    __syncthreads();
    int i = blockIdx.x * blockDim.x + threadIdx.x;
    if (i < EE) atomicAdd(&sc[rel[i]], 1);
    __syncthreads();
    if (threadIdx.x < RRR && sc[threadIdx.x])
        atomicAdd(&g_count[threadIdx.x], sc[threadIdx.x]);
}

// 24-iteration prefix only — tile table written in parallel by tilefill_k
__global__ void scan_k() {
    if (threadIdx.x != 0) return;
    int s = 0, tb = 0;
    for (int b = 0; b < NB; b++) {
        int c = g_count[(b < RRR) ? b : (b - RRR)];
        g_start[b]  = s;
        g_cursor[b] = s;
        g_tbase[b]  = tb;
        tb += (c + TM - 1) / TM;
        s += c;
    }
    g_start[NB] = s;
    g_tbase[NB] = tb;
    g_total_tiles = tb;
}

// parallel tile-table fill: thread i -> (bucket, m-tile) via 24-entry lookup
__global__ void tilefill_k() {
    __shared__ int tb[NB + 1];
    if (threadIdx.x <= NB) tb[threadIdx.x] = g_tbase[threadIdx.x];
    __syncthreads();
    int i = blockIdx.x * blockDim.x + threadIdx.x;
    if (i >= g_total_tiles) return;
    int b = 0;
#pragma unroll
    for (int k = 0; k < NB - 1; k++) b += (i >= tb[b + 1]) ? 1 : 0;
    g_tile_info[i] = (b << 16) | (i - tb[b]);
}

// block-aggregated scatter: smem local offsets + one global atomic per (block,bucket)
__global__ void scatter2_k(const int* __restrict__ dep,
                           const int* __restrict__ rel,
                           const int* __restrict__ gov) {
    __shared__ int sc[NB];
    __shared__ int base[NB];
    int t = threadIdx.x;
    if (t < NB) sc[t] = 0;
    __syncthreads();
    int i = blockIdx.x * blockDim.x + t;
    int r = 0, d = 0, g = 0, l1 = 0, l2 = 0;
    bool v = (i < EE);
    if (v) {
        r = rel[i]; d = dep[i]; g = gov[i];
        l1 = atomicAdd(&sc[r], 1);
        l2 = atomicAdd(&sc[r + RRR], 1);
    }
    __syncthreads();
    if (t < NB) base[t] = sc[t] ? atomicAdd(&g_cursor[t], sc[t]) : 0;
    __syncthreads();
    if (v) {
        int p = base[r] + l1;         g_src[p] = g; g_dst[p] = d;   // forward
        int q = base[r + RRR] + l2;   g_src[q] = d; g_dst[q] = g;   // reverse
    }
}

// ---------------- grouped GEMM via mma.sync (HMMA) ----------------------------
// CTA: 128(M) x 128(N); grid.y in {0,1} selects N half. 8 warps, warp tile 32x64.
// Single fp16 pass; K=256 as 4 chunks in a 3-stage cp.async ring with EARLY
// refill (issued before the chunk's MMAs) and one barrier per chunk.
template<bool SELF>
__global__ __launch_bounds__(256, 2)
void gemm_mma_k(const float* __restrict__ bvec_g, float* __restrict__ out) {
    extern __shared__ char smem[];
    const int tid = threadIdx.x, lid = tid & 31, wid = tid >> 5;
    const int wm = wid >> 1, wn = wid & 1;          // warp grid 4 x 2
    const int n0 = blockIdx.y * 128;

    int b = 0, m0, start = 0, count;
    if (SELF) {
        m0 = blockIdx.x * TM;
        count = NNODE;
    } else {
        if (blockIdx.x >= g_total_tiles) return;
        int info = g_tile_info[blockIdx.x];
        b = info >> 16;
        m0 = (info & 0xFFFF) * TM;
        start = g_start[b];
        count = g_start[b + 1] - start;
    }

    int*   row_src = (int*)smem;
    int*   row_dst = (int*)(smem + SM_ROWDST);
    float* bias    = (float*)(smem + SM_BIAS);
    uint32_t sb = smem_u32(smem);

    if (tid < 128) {
        int m = m0 + tid; if (m >= count) m = count - 1;
        int s, d;
        if (SELF) { s = m; d = m; }
        else      { s = g_src[start + m]; d = g_dst[start + m]; }
        row_src[tid] = s;
        row_dst[tid] = d;
        bias[tid] = SELF ? bvec_g[n0 + tid] : bvec_g[b * DD + n0 + tid];
    }
    __syncthreads();

    const __half* Bsrc = g_wh + (size_t)(SELF ? NB : b) * DD * DD + (size_t)n0 * DD;

    // fill one k64 chunk into stage s (A: gathered rows; B: weight rows [n][k])
    auto fill = [&](int c, int s) {
        int k0 = c * 64;
        uint32_t base = sb + SM_BUF + (uint32_t)s * STAGE_STRIDE;
#pragma unroll
        for (int i = 0; i < 8; i++) {
            int u = tid + 256 * i;
            int row = (u >> 3) & 127;
            int c16 = u & 7;
            uint32_t dsto = (uint32_t)(row * 8 + (c16 ^ (row & 7))) * 16;
            if (u < 1024)
                cp16(base + dsto, g_xh + (size_t)row_src[row] * DD + k0 + c16 * 8);
            else
                cp16(base + OFF_B + dsto, Bsrc + (size_t)row * DD + k0 + c16 * 8);
        }
        cp_commit();
    };

    float acc[2][8][4];
#pragma unroll
    for (int mi = 0; mi < 2; mi++)
#pragma unroll
        for (int j = 0; j < 8; j++)
#pragma unroll
            for (int q = 0; q < 4; q++) acc[mi][j][q] = 0.f;

    fill(0, 0);
    fill(1, 1);

#pragma unroll 1
    for (int c = 0; c < NCHUNK; c++) {
        int s = c % NSTAGE;
        if (c < NCHUNK - 1) cp_wait<1>(); else cp_wait<0>();
        __syncthreads();
        // EARLY refill: stage (c+2)%3 was last consumed at iteration c-1; the
        // barrier above separates those reads from this write. The copy then
        // overlaps this chunk's MMA work instead of the next chunk's budget.
        if (c + 2 < NCHUNK) fill(c + 2, (c + 2) % NSTAGE);

        uint32_t ab = sb + SM_BUF + (uint32_t)s * STAGE_STRIDE;
        uint32_t bb = ab + OFF_B;
#pragma unroll
        for (int ks = 0; ks < 4; ks++) {
            uint32_t a[2][4];
            {
                int sub = lid >> 3, r8 = lid & 7;
                int c16 = ks * 2 + (sub >> 1);
#pragma unroll
                for (int mi = 0; mi < 2; mi++) {
                    int row = wm * 32 + mi * 16 + (sub & 1) * 8 + r8;
                    ldsm4(a[mi], ab + (uint32_t)(row * 8 + (c16 ^ (row & 7))) * 16);
                }
            }
#pragma unroll
            for (int nj = 0; nj < 4; nj++) {
                uint32_t bf[4];
                int grp = lid >> 4, half = (lid >> 3) & 1, r8 = lid & 7;
                int nrow = wn * 64 + nj * 16 + grp * 8 + r8;
                int c16 = ks * 2 + half;
                ldsm4(bf, bb + (uint32_t)(nrow * 8 + (c16 ^ (nrow & 7))) * 16);
#pragma unroll
                for (int mi = 0; mi < 2; mi++) {
                    mma16816(acc[mi][nj * 2 + 0], a[mi], bf[0], bf[1]);
                    mma16816(acc[mi][nj * 2 + 1], a[mi], bf[2], bf[3]);
                }
            }
        }
        // no trailing barrier: 3-stage ring guarantees the next write target
        // was consumed a full iteration ago.
    }

    // ---- epilogue: bias + lane-pair merged float4/red4 -----------------------
    const int rbase = wm * 32 + (lid >> 2);
    const int cgrp  = lid & 3;
#pragma unroll
    for (int mi = 0; mi < 2; mi++) {
#pragma unroll
        for (int half = 0; half < 2; half++) {
            int rl = rbase + mi * 16 + half * 8;
            bool ok = (m0 + rl) < count;
            int dst = SELF ? (m0 + rl) : row_dst[rl];
            float* orow = out + (size_t)dst * DD + n0;
#pragma unroll
            for (int j = 0; j < 8; j++) {
                int col = 2 * cgrp + j * 8;
                float v0 = acc[mi][j][half * 2 + 0] + bias[wn * 64 + col];
                float v1 = acc[mi][j][half * 2 + 1] + bias[wn * 64 + col + 1];
                float o0 = __shfl_xor_sync(0xffffffffu, v0, 1);
                float o1 = __shfl_xor_sync(0xffffffffu, v1, 1);
                if (ok && !(lid & 1)) {
                    int c4 = wn * 64 + j * 8 + ((cgrp == 0) ? 0 : 4);
                    if (SELF) {
                        float4 v; v.x = v0; v.y = v1; v.z = o0; v.w = o1;
                        *(float4*)(orow + c4) = v;
                    } else {
                        red4(orow + c4, v0, v1, o0, o1);
                    }
                }
            }
        }
    }
}

// ---------------- final ReLU -------------------------------------------------
__global__ void relu_k(float* __restrict__ out) {
    int i = blockIdx.x * blockDim.x + threadIdx.x;
    if (i < NNODE * DD / 4) {
        float4* p = (float4*)out;
        float4 v = p[i];
        v.x = fmaxf(v.x, 0.f); v.y = fmaxf(v.y, 0.f);
        v.z = fmaxf(v.z, 0.f); v.w = fmaxf(v.w, 0.f);
        p[i] = v;
    }
}

// ---------------- launch -----------------------------------------------------
extern "C" void kernel_launch(void* const* d_in, const int* in_sizes, int n_in,
                              void* d_out, int out_size) {
    (void)in_sizes; (void)n_in; (void)out_size;
    const float* x   = (const float*)d_in[0];
    const int*   dep = (const int*)d_in[1];
    const int*   rel = (const int*)d_in[2];
    const int*   gov = (const int*)d_in[3];
    const float* Ws  = (const float*)d_in[4];
    const float* bs  = (const float*)d_in[5];
    const float* Wr  = (const float*)d_in[6];
    const float* br  = (const float*)d_in[7];
    float* out = (float*)d_out;

    cudaFuncSetAttribute(gemm_mma_k<true>,  cudaFuncAttributeMaxDynamicSharedMemorySize, SMEM_TOTAL);
    cudaFuncSetAttribute(gemm_mma_k<false>, cudaFuncAttributeMaxDynamicSharedMemorySize, SMEM_TOTAL);

    // fused prep first (also zeroes g_count for hist)
    convert_all_k<<<(XW_TOTAL + 255) / 256, 256>>>(x, Wr, Ws);

    // bucketing: hist -> 24-entry scan -> parallel tile table -> scatter
    hist_k<<<(EE + 255) / 256, 256>>>(rel);
    scan_k<<<1, 32>>>();
    tilefill_k<<<(MAX_TILES + 255) / 256, 256>>>();
    scatter2_k<<<(EE + 255) / 256, 256>>>(dep, rel, gov);

    // self transform (plain stores initialize out)
    dim3 gself((NNODE + TM - 1) / TM, 2);
    gemm_mma_k<true><<<gself, 256, SMEM_TOTAL>>>(bs, out);

    // grouped message GEMM (+ atomic scatter-add)
    dim3 gmsg(MAX_TILES, 2);
    gemm_mma_k<false><<<gmsg, 256, SMEM_TOTAL>>>(br, out);

    relu_k<<<(NNODE * DD / 4 + 255) / 256, 256>>>(out);
}

// round 17
// speedup vs baseline: 1.1747x; 1.0203x over previous
#include <cuda_runtime.h>
#include <cuda_fp16.h>
#include <cstdint>

// ---------------- problem constants -----------------------------------------
#define DD    256
#define NNODE 20000
#define RRR   12
#define EE    200000
#define NB    (2*RRR)
#define TM    128
#define MAX_TILES (2*EE/TM + NB + 8)
#define NCHUNK 4             // single fp16 pass: 4 x k64 chunks (K=256)

// ---------------- smem layout -------------------------------------------------
#define SM_ROWSRC 0          // 128 int
#define SM_ROWDST 512        // 128 int
#define SM_BIAS   1024       // 128 float
#define SM_BUF    2048
#define STAGE_STRIDE 32768   // A 16KB + B 16KB
#define OFF_B     16384
#define NSTAGE    3
#define SMEM_TOTAL (SM_BUF + NSTAGE*STAGE_STRIDE)   // 100352 B -> occ 2, 16 warps/SM

// ---------------- device scratch ---------------------------------------------
__device__ int g_count[RRR];
__device__ int g_start[NB + 1];
__device__ int g_cursor[NB];
__device__ int g_tbase[NB + 1];       // tile-count prefix per bucket
__device__ int g_src[2 * EE];
__device__ int g_dst[2 * EE];
__device__ int g_tile_info[MAX_TILES];
__device__ int g_total_tiles;

__device__ __half g_xh[NNODE * DD];
__device__ __half g_wh[(NB + 1) * DD * DD];   // [bucket][out=n][in=k]; index NB = W_self

// ---------------- PTX helpers ------------------------------------------------
__device__ __forceinline__ uint32_t smem_u32(const void* p) {
    uint32_t a;
    asm("{ .reg .u64 t; cvta.to.shared.u64 t, %1; cvt.u32.u64 %0, t; }" : "=r"(a) : "l"(p));
    return a;
}
__device__ __forceinline__ void cp16(uint32_t d, const void* s) {
    asm volatile("cp.async.cg.shared.global [%0], [%1], 16;" :: "r"(d), "l"(s) : "memory");
}
__device__ __forceinline__ void cp_commit() {
    asm volatile("cp.async.commit_group;" ::: "memory");
}
template<int N> __device__ __forceinline__ void cp_wait() {
    asm volatile("cp.async.wait_group %0;" :: "n"(N) : "memory");
}
__device__ __forceinline__ void ldsm4(uint32_t* r, uint32_t addr) {
    asm volatile("ldmatrix.sync.aligned.m8n8.x4.shared.b16 {%0,%1,%2,%3}, [%4];"
                 : "=r"(r[0]), "=r"(r[1]), "=r"(r[2]), "=r"(r[3]) : "r"(addr));
}
__device__ __forceinline__ void mma16816(float* c, const uint32_t* a, uint32_t b0, uint32_t b1) {
    asm volatile("mma.sync.aligned.m16n8k16.row.col.f32.f16.f16.f32 "
                 "{%0,%1,%2,%3}, {%4,%5,%6,%7}, {%8,%9}, {%0,%1,%2,%3};"
                 : "+f"(c[0]), "+f"(c[1]), "+f"(c[2]), "+f"(c[3])
                 : "r"(a[0]), "r"(a[1]), "r"(a[2]), "r"(a[3]), "r"(b0), "r"(b1));
}
__device__ __forceinline__ void red4(float* p, float a, float b, float c, float d) {
    asm volatile("red.global.add.v4.f32 [%0], {%1,%2,%3,%4};"
                 :: "l"(p), "f"(a), "f"(b), "f"(c), "f"(d) : "memory");
}

// ---------------- prep: fp16 converts (no count zeroing here) -----------------
#define XW_TOTAL (NNODE * DD + (NB + 1) * DD * DD)
__global__ void convert_all_k(const float* __restrict__ x,
                              const float* __restrict__ Wr,
                              const float* __restrict__ Ws) {
    int i = blockIdx.x * blockDim.x + threadIdx.x;
    if (i >= XW_TOTAL) return;
    if (i < NNODE * DD) {
        g_xh[i] = __float2half_rn(x[i]);
    } else {
        int j = i - NNODE * DD;
        int b = j >> 16;
        g_wh[j] = __float2half_rn((b < NB) ? Wr[j] : Ws[j & 65535]);
    }
}

// ---------------- bucketing chain (independent of converts) -------------------
__global__ void zero_counts_k() {
    if (threadIdx.x < RRR) g_count[threadIdx.x] = 0;
}

__global__ void hist_k(const int* __restrict__ rel) {
    __shared__ int sc[RRR];
    if (threadIdx.x < RRR) sc[threadIdx.x] = 0;
    __syncthreads();
    int i = blockIdx.x * blockDim.x + threadIdx.x;
    if (i < EE) atomicAdd(&sc[rel[i]], 1);
    __syncthreads();
    if (threadIdx.x < RRR && sc[threadIdx.x])
        atomicAdd(&g_count[threadIdx.x], sc[threadIdx.x]);
}

// 24-iteration prefix only — tile table written in parallel by tilefill_k
__global__ void scan_k() {
    if (threadIdx.x != 0) return;
    int s = 0, tb = 0;
    for (int b = 0; b < NB; b++) {
        int c = g_count[(b < RRR) ? b : (b - RRR)];
        g_start[b]  = s;
        g_cursor[b] = s;
        g_tbase[b]  = tb;
        tb += (c + TM - 1) / TM;
        s += c;
    }
    g_start[NB] = s;
    g_tbase[NB] = tb;
    g_total_tiles = tb;
}

// parallel tile-table fill: thread i -> (bucket, m-tile) via 24-entry lookup
__global__ void tilefill_k() {
    __shared__ int tb[NB + 1];
    if (threadIdx.x <= NB) tb[threadIdx.x] = g_tbase[threadIdx.x];
    __syncthreads();
    int i = blockIdx.x * blockDim.x + threadIdx.x;
    if (i >= g_total_tiles) return;
    int b = 0;
#pragma unroll
    for (int k = 0; k < NB - 1; k++) b += (i >= tb[b + 1]) ? 1 : 0;
    g_tile_info[i] = (b << 16) | (i - tb[b]);
}

// block-aggregated scatter: smem local offsets + one global atomic per (block,bucket)
__global__ void scatter2_k(const int* __restrict__ dep,
                           const int* __restrict__ rel,
                           const int* __restrict__ gov) {
    __shared__ int sc[NB];
    __shared__ int base[NB];
    int t = threadIdx.x;
    if (t < NB) sc[t] = 0;
    __syncthreads();
    int i = blockIdx.x * blockDim.x + t;
    int r = 0, d = 0, g = 0, l1 = 0, l2 = 0;
    bool v = (i < EE);
    if (v) {
        r = rel[i]; d = dep[i]; g = gov[i];
        l1 = atomicAdd(&sc[r], 1);
        l2 = atomicAdd(&sc[r + RRR], 1);
    }
    __syncthreads();
    if (t < NB) base[t] = sc[t] ? atomicAdd(&g_cursor[t], sc[t]) : 0;
    __syncthreads();
    if (v) {
        int p = base[r] + l1;         g_src[p] = g; g_dst[p] = d;   // forward
        int q = base[r + RRR] + l2;   g_src[q] = d; g_dst[q] = g;   // reverse
    }
}

// ---------------- grouped GEMM via mma.sync (HMMA) ----------------------------
// CTA: 128(M) x 128(N); grid.y in {0,1} selects N half. 8 warps, warp tile 32x64.
// Single fp16 pass; K=256 as 4 chunks in a 3-stage cp.async ring with EARLY
// refill (issued before the chunk's MMAs) and one barrier per chunk.
template<bool SELF>
__global__ __launch_bounds__(256, 2)
void gemm_mma_k(const float* __restrict__ bvec_g, float* __restrict__ out) {
    extern __shared__ char smem[];
    const int tid = threadIdx.x, lid = tid & 31, wid = tid >> 5;
    const int wm = wid >> 1, wn = wid & 1;          // warp grid 4 x 2
    const int n0 = blockIdx.y * 128;

    int b = 0, m0, start = 0, count;
    if (SELF) {
        m0 = blockIdx.x * TM;
        count = NNODE;
    } else {
        if (blockIdx.x >= g_total_tiles) return;
        int info = g_tile_info[blockIdx.x];
        b = info >> 16;
        m0 = (info & 0xFFFF) * TM;
        start = g_start[b];
        count = g_start[b + 1] - start;
    }

    int*   row_src = (int*)smem;
    int*   row_dst = (int*)(smem + SM_ROWDST);
    float* bias    = (float*)(smem + SM_BIAS);
    uint32_t sb = smem_u32(smem);

    if (tid < 128) {
        int m = m0 + tid; if (m >= count) m = count - 1;
        int s, d;
        if (SELF) { s = m; d = m; }
        else      { s = g_src[start + m]; d = g_dst[start + m]; }
        row_src[tid] = s;
        row_dst[tid] = d;
        bias[tid] = SELF ? bvec_g[n0 + tid] : bvec_g[b * DD + n0 + tid];
    }
    __syncthreads();

    const __half* Bsrc = g_wh + (size_t)(SELF ? NB : b) * DD * DD + (size_t)n0 * DD;

    // fill one k64 chunk into stage s (A: gathered rows; B: weight rows [n][k])
    auto fill = [&](int c, int s) {
        int k0 = c * 64;
        uint32_t base = sb + SM_BUF + (uint32_t)s * STAGE_STRIDE;
#pragma unroll
        for (int i = 0; i < 8; i++) {
            int u = tid + 256 * i;
            int row = (u >> 3) & 127;
            int c16 = u & 7;
            uint32_t dsto = (uint32_t)(row * 8 + (c16 ^ (row & 7))) * 16;
            if (u < 1024)
                cp16(base + dsto, g_xh + (size_t)row_src[row] * DD + k0 + c16 * 8);
            else
                cp16(base + OFF_B + dsto, Bsrc + (size_t)row * DD + k0 + c16 * 8);
        }
        cp_commit();
    };

    float acc[2][8][4];
#pragma unroll
    for (int mi = 0; mi < 2; mi++)
#pragma unroll
        for (int j = 0; j < 8; j++)
#pragma unroll
            for (int q = 0; q < 4; q++) acc[mi][j][q] = 0.f;

    fill(0, 0);
    fill(1, 1);

#pragma unroll 1
    for (int c = 0; c < NCHUNK; c++) {
        int s = c % NSTAGE;
        if (c < NCHUNK - 1) cp_wait<1>(); else cp_wait<0>();
        __syncthreads();
        // EARLY refill: stage (c+2)%3 was last consumed at iteration c-1; the
        // barrier above separates those reads from this write. The copy then
        // overlaps this chunk's MMA work instead of the next chunk's budget.
        if (c + 2 < NCHUNK) fill(c + 2, (c + 2) % NSTAGE);

        uint32_t ab = sb + SM_BUF + (uint32_t)s * STAGE_STRIDE;
        uint32_t bb = ab + OFF_B;
#pragma unroll
        for (int ks = 0; ks < 4; ks++) {
            uint32_t a[2][4];
            {
                int sub = lid >> 3, r8 = lid & 7;
                int c16 = ks * 2 + (sub >> 1);
#pragma unroll
                for (int mi = 0; mi < 2; mi++) {
                    int row = wm * 32 + mi * 16 + (sub & 1) * 8 + r8;
                    ldsm4(a[mi], ab + (uint32_t)(row * 8 + (c16 ^ (row & 7))) * 16);
                }
            }
#pragma unroll
            for (int nj = 0; nj < 4; nj++) {
                uint32_t bf[4];
                int grp = lid >> 4, half = (lid >> 3) & 1, r8 = lid & 7;
                int nrow = wn * 64 + nj * 16 + grp * 8 + r8;
                int c16 = ks * 2 + half;
                ldsm4(bf, bb + (uint32_t)(nrow * 8 + (c16 ^ (nrow & 7))) * 16);
#pragma unroll
                for (int mi = 0; mi < 2; mi++) {
                    mma16816(acc[mi][nj * 2 + 0], a[mi], bf[0], bf[1]);
                    mma16816(acc[mi][nj * 2 + 1], a[mi], bf[2], bf[3]);
                }
            }
        }
        // no trailing barrier: 3-stage ring guarantees the next write target
        // was consumed a full iteration ago.
    }

    // ---- epilogue: bias + lane-pair merged float4/red4 -----------------------
    const int rbase = wm * 32 + (lid >> 2);
    const int cgrp  = lid & 3;
#pragma unroll
    for (int mi = 0; mi < 2; mi++) {
#pragma unroll
        for (int half = 0; half < 2; half++) {
            int rl = rbase + mi * 16 + half * 8;
            bool ok = (m0 + rl) < count;
            int dst = SELF ? (m0 + rl) : row_dst[rl];
            float* orow = out + (size_t)dst * DD + n0;
#pragma unroll
            for (int j = 0; j < 8; j++) {
                int col = 2 * cgrp + j * 8;
                float v0 = acc[mi][j][half * 2 + 0] + bias[wn * 64 + col];
                float v1 = acc[mi][j][half * 2 + 1] + bias[wn * 64 + col + 1];
                float o0 = __shfl_xor_sync(0xffffffffu, v0, 1);
                float o1 = __shfl_xor_sync(0xffffffffu, v1, 1);
                if (ok && !(lid & 1)) {
                    int c4 = wn * 64 + j * 8 + ((cgrp == 0) ? 0 : 4);
                    if (SELF) {
                        float4 v; v.x = v0; v.y = v1; v.z = o0; v.w = o1;
                        *(float4*)(orow + c4) = v;
                    } else {
                        red4(orow + c4, v0, v1, o0, o1);
                    }
                }
            }
        }
    }
}

// ---------------- final ReLU -------------------------------------------------
__global__ void relu_k(float* __restrict__ out) {
    int i = blockIdx.x * blockDim.x + threadIdx.x;
    if (i < NNODE * DD / 4) {
        float4* p = (float4*)out;
        float4 v = p[i];
        v.x = fmaxf(v.x, 0.f); v.y = fmaxf(v.y, 0.f);
        v.z = fmaxf(v.z, 0.f); v.w = fmaxf(v.w, 0.f);
        p[i] = v;
    }
}

// ---------------- launch: fork bucketing onto a side stream -------------------
extern "C" void kernel_launch(void* const* d_in, const int* in_sizes, int n_in,
                              void* d_out, int out_size) {
    (void)in_sizes; (void)n_in; (void)out_size;
    const float* x   = (const float*)d_in[0];
    const int*   dep = (const int*)d_in[1];
    const int*   rel = (const int*)d_in[2];
    const int*   gov = (const int*)d_in[3];
    const float* Ws  = (const float*)d_in[4];
    const float* bs  = (const float*)d_in[5];
    const float* Wr  = (const float*)d_in[6];
    const float* br  = (const float*)d_in[7];
    float* out = (float*)d_out;

    // one-time resources (constant handles; identical work every call)
    static cudaStream_t s2 = nullptr;
    static cudaEvent_t  ev_fork = nullptr, ev_join = nullptr;
    static bool init_done = false;
    if (!init_done) {
        cudaStreamCreateWithFlags(&s2, cudaStreamNonBlocking);
        cudaEventCreateWithFlags(&ev_fork, cudaEventDisableTiming);
        cudaEventCreateWithFlags(&ev_join, cudaEventDisableTiming);
        cudaFuncSetAttribute(gemm_mma_k<true>,  cudaFuncAttributeMaxDynamicSharedMemorySize, SMEM_TOTAL);
        cudaFuncSetAttribute(gemm_mma_k<false>, cudaFuncAttributeMaxDynamicSharedMemorySize, SMEM_TOTAL);
        init_done = true;
    }

    // fork: bucketing chain (depends only on rel/dep/gov) on side stream
    cudaEventRecord(ev_fork, 0);
    cudaStreamWaitEvent(s2, ev_fork, 0);
    zero_counts_k<<<1, 32, 0, s2>>>();
    hist_k<<<(EE + 255) / 256, 256, 0, s2>>>(rel);
    scan_k<<<1, 32, 0, s2>>>();
    tilefill_k<<<(MAX_TILES + 255) / 256, 256, 0, s2>>>();
    scatter2_k<<<(EE + 255) / 256, 256, 0, s2>>>(dep, rel, gov);
    cudaEventRecord(ev_join, s2);

    // main stream: converts + self transform (independent of bucketing)
    convert_all_k<<<(XW_TOTAL + 255) / 256, 256>>>(x, Wr, Ws);
    dim3 gself((NNODE + TM - 1) / TM, 2);
    gemm_mma_k<true><<<gself, 256, SMEM_TOTAL>>>(bs, out);

    // join: msg GEMM needs bucketing + converts + self-initialized out
    cudaStreamWaitEvent(0, ev_join, 0);
    dim3 gmsg(MAX_TILES, 2);
    gemm_mma_k<false><<<gmsg, 256, SMEM_TOTAL>>>(br, out);

    relu_k<<<(NNODE * DD / 4 + 255) / 256, 256>>>(out);
}